// round 16
// baseline (speedup 1.0000x reference)
#include <cuda_runtime.h>
#include <cuda_bf16.h>
#include <cstdint>

#define D_MODEL 2048
#define NHEAD   16
#define HD      128
#define TSEQ    1024
#define BATCH   4
#define MTOT    (BATCH * TSEQ)     // 4096
#define NQKV    (3 * D_MODEL)      // 6144

// ---------------------------------------------------------------------------
// Scratch (__device__ globals — allocation-guard safe), 16B-aligned
// ---------------------------------------------------------------------------
__device__ __align__(16) __nv_bfloat16 g_qkvhi[MTOT * NQKV];
__device__ __align__(16) __nv_bfloat16 g_qkvlo[MTOT * NQKV];
__device__ __align__(16) __nv_bfloat16 g_xhi[MTOT * D_MODEL];
__device__ __align__(16) __nv_bfloat16 g_xlo[MTOT * D_MODEL];
__device__ __align__(16) __nv_bfloat16 g_ahi[MTOT * D_MODEL];
__device__ __align__(16) __nv_bfloat16 g_alo[MTOT * D_MODEL];
__device__ __align__(16) __nv_bfloat16 g_wqhi[NQKV * D_MODEL];
__device__ __align__(16) __nv_bfloat16 g_wqlo[NQKV * D_MODEL];
__device__ __align__(16) __nv_bfloat16 g_wphi[D_MODEL * D_MODEL];
__device__ __align__(16) __nv_bfloat16 g_wplo[D_MODEL * D_MODEL];

// ---------------------------------------------------------------------------
// helpers
// ---------------------------------------------------------------------------
__device__ __forceinline__ uint32_t smem_u32(const void* p) {
    uint32_t a;
    asm("{ .reg .u64 t; cvta.to.shared.u64 t, %1; cvt.u32.u64 %0, t; }"
        : "=r"(a) : "l"(p));
    return a;
}
__device__ __forceinline__ void cpa16(uint32_t dst, const void* src) {
    asm volatile("cp.async.cg.shared.global [%0], [%1], 16;" :: "r"(dst), "l"(src));
}
__device__ __forceinline__ void cp_commit() { asm volatile("cp.async.commit_group;"); }
template <int N> __device__ __forceinline__ void cp_wait() {
    asm volatile("cp.async.wait_group %0;" :: "n"(N));
}
__device__ __forceinline__ void ldsm4(uint32_t* r, uint32_t a) {
    asm volatile("ldmatrix.sync.aligned.m8n8.x4.shared.b16 {%0,%1,%2,%3}, [%4];"
        : "=r"(r[0]), "=r"(r[1]), "=r"(r[2]), "=r"(r[3]) : "r"(a));
}
__device__ __forceinline__ void ldsm4t(uint32_t* r, uint32_t a) {
    asm volatile("ldmatrix.sync.aligned.m8n8.x4.trans.shared.b16 {%0,%1,%2,%3}, [%4];"
        : "=r"(r[0]), "=r"(r[1]), "=r"(r[2]), "=r"(r[3]) : "r"(a));
}
__device__ __forceinline__ void mma_bf16(float* c, const uint32_t* a,
                                         const uint32_t* b) {
    asm volatile(
        "mma.sync.aligned.m16n8k16.row.col.f32.bf16.bf16.f32 "
        "{%0,%1,%2,%3}, {%4,%5,%6,%7}, {%8,%9}, {%0,%1,%2,%3};"
        : "+f"(c[0]), "+f"(c[1]), "+f"(c[2]), "+f"(c[3])
        : "r"(a[0]), "r"(a[1]), "r"(a[2]), "r"(a[3]), "r"(b[0]), "r"(b[1]));
}
__device__ __forceinline__ uint32_t packbf(float e0, float e1) {
    uint32_t r;
    asm("cvt.rn.bf16x2.f32 %0, %1, %2;" : "=r"(r) : "f"(e1), "f"(e0));
    return r;
}
__device__ __forceinline__ uint32_t lopackbf(uint32_t hipack, float e0, float e1) {
    float h0 = __uint_as_float(hipack << 16);
    float h1 = __uint_as_float(hipack & 0xffff0000u);
    return packbf(e0 - h0, e1 - h1);
}
__device__ __forceinline__ float ex2f(float x) {
    float y;
    asm("ex2.approx.ftz.f32 %0, %1;" : "=f"(y) : "f"(x));
    return y;
}
// 64B-row swizzle: bits [4:5] ^= bits [7:8]; apply to full sub-bit-10 offset.
__device__ __forceinline__ uint32_t swz(uint32_t off) {
    return off ^ (((off >> 7) & 3u) << 4);
}

// ---------------------------------------------------------------------------
// Split fp32 -> (hi, lo) bf16 (elementwise)
// ---------------------------------------------------------------------------
__global__ __launch_bounds__(256)
void split_kernel(const float* __restrict__ in, __nv_bfloat16* __restrict__ hi,
                  __nv_bfloat16* __restrict__ lo, int n)
{
    int i = (blockIdx.x * 256 + threadIdx.x) * 4;
    if (i >= n) return;
    float4 v = *(const float4*)(in + i);
    uint32_t h0 = packbf(v.x, v.y);
    uint32_t h1 = packbf(v.z, v.w);
    *(uint32_t*)(hi + i)     = h0;
    *(uint32_t*)(hi + i + 2) = h1;
    *(uint32_t*)(lo + i)     = lopackbf(h0, v.x, v.y);
    *(uint32_t*)(lo + i + 2) = lopackbf(h1, v.z, v.w);
}

// ---------------------------------------------------------------------------
// Transpose + split: W fp32 [K][N] -> Whi/Wlo bf16 [N][K]
// ---------------------------------------------------------------------------
__global__ __launch_bounds__(256)
void tsplit_kernel(const float* __restrict__ W, __nv_bfloat16* __restrict__ hi,
                   __nv_bfloat16* __restrict__ lo, int K, int N)
{
    __shared__ float t[32][33];
    const int n0 = blockIdx.x * 32, k0 = blockIdx.y * 32;
    const int x = threadIdx.x & 31, y = threadIdx.x >> 5;
#pragma unroll
    for (int i = 0; i < 4; i++)
        t[y + 8 * i][x] = W[(size_t)(k0 + y + 8 * i) * N + n0 + x];
    __syncthreads();
#pragma unroll
    for (int i = 0; i < 4; i++) {
        float v = t[x][y + 8 * i];
        __nv_bfloat16 h = __float2bfloat16(v);
        size_t o = (size_t)(n0 + y + 8 * i) * K + k0 + x;
        hi[o] = h;
        lo[o] = __float2bfloat16(v - __bfloat162float(h));
    }
}

// ---------------------------------------------------------------------------
// HMMA bf16x3 GEMM — R9/R11 pipeline with loop-invariant load addressing:
// per-thread swizzled dst offset precomputed once (t=1 dst = +4096, commutes
// with swz), 4 global pointers advanced +32 elements per issued chunk.
// ---------------------------------------------------------------------------
#define BKC        32
#define OPB        (128 * 64)
#define STGB       (4 * OPB)
#define NSTG       3
#define GEMM_SMEM  (NSTG * STGB)

__global__ __launch_bounds__(256, 2)
void gemm_hmma(const __nv_bfloat16* __restrict__ Ahi,
               const __nv_bfloat16* __restrict__ Alo,
               const __nv_bfloat16* __restrict__ Bhi,
               const __nv_bfloat16* __restrict__ Blo,
               float* __restrict__ Cf,
               __nv_bfloat16* __restrict__ Chi,
               __nv_bfloat16* __restrict__ Clo,
               int M, int N, int K)
{
    extern __shared__ char smc[];
    const uint32_t sb = smem_u32(smc);
    const int tid  = threadIdx.x;
    const int wid  = tid >> 5, lane = tid & 31;
    const int wm   = wid >> 2;
    const int wn   = wid & 3;
    const int g    = lane >> 2;
    const int tig  = lane & 3;
    const int m0 = blockIdx.y * 128, n0 = blockIdx.x * 128;

    const int lrow  = lane & 15;
    const int lhalf = lane >> 4;
    const int brow  = (lane & 7) | ((lane & 16) >> 1);
    const int bhalf = (lane >> 3) & 1;

    uint32_t aoff[2], boff[2];
#pragma unroll
    for (int ks = 0; ks < 2; ks++) {
        aoff[ks] = swz((uint32_t)((wm * 64 + lrow) * 64 + lhalf * 16 + ks * 32));
        boff[ks] = swz((uint32_t)((wn * 32 + brow) * 64 + bhalf * 16 + ks * 32));
    }

    // ---- loop-invariant load addressing ----
    // thread covers rows {row, row+64}, k-slice seg*16B; t=1 dst = t=0 dst + 4096
    const int lrw = tid >> 2, seg = tid & 3;
    const uint32_t swd = swz((uint32_t)(lrw * 64 + seg * 16));
    const size_t rstep = (size_t)64 * (size_t)K;          // +64 rows
    const __nv_bfloat16* gp0 = Ahi + (size_t)(m0 + lrw) * K + seg * 8;
    const __nv_bfloat16* gp1 = Alo + (size_t)(m0 + lrw) * K + seg * 8;
    const __nv_bfloat16* gp2 = Bhi + (size_t)(n0 + lrw) * K + seg * 8;
    const __nv_bfloat16* gp3 = Blo + (size_t)(n0 + lrw) * K + seg * 8;

    float acc[4][4][4];
#pragma unroll
    for (int mt = 0; mt < 4; mt++)
#pragma unroll
        for (int nt = 0; nt < 4; nt++)
#pragma unroll
            for (int q = 0; q < 4; q++) acc[mt][nt][q] = 0.0f;

    const int NC = K / BKC;

    // issue one stage's 8 copies and advance pointers by BKC elements
#define ISSUE_STAGE(stb) do {                                             \
        cpa16((stb) + swd,                 gp0);                          \
        cpa16((stb) + swd + 4096,          gp0 + rstep);                  \
        cpa16((stb) + OPB + swd,           gp1);                          \
        cpa16((stb) + OPB + swd + 4096,    gp1 + rstep);                  \
        cpa16((stb) + 2u * OPB + swd,        gp2);                        \
        cpa16((stb) + 2u * OPB + swd + 4096, gp2 + rstep);                \
        cpa16((stb) + 3u * OPB + swd,        gp3);                        \
        cpa16((stb) + 3u * OPB + swd + 4096, gp3 + rstep);                \
        gp0 += BKC; gp1 += BKC; gp2 += BKC; gp3 += BKC;                   \
        cp_commit();                                                      \
    } while (0)

    ISSUE_STAGE(sb);
    ISSUE_STAGE(sb + STGB);

    int st_idx = 0;
    for (int kc = 0; kc < NC; kc++) {
        if (kc + 1 < NC) cp_wait<1>(); else cp_wait<0>();
        __syncthreads();   // chunk kc visible; all warps done with kc-1

        if (kc + 2 < NC) {
            int nst = st_idx + 2; if (nst >= NSTG) nst -= NSTG;
            ISSUE_STAGE(sb + (uint32_t)nst * STGB);
        }

        const uint32_t st = sb + (uint32_t)st_idx * STGB;
#pragma unroll
        for (int ks = 0; ks < 2; ks++) {
            const uint32_t aB = st + aoff[ks];
            const uint32_t bB = st + 2u * OPB + boff[ks];

            uint32_t bh[2][4], bl[2][4];
#pragma unroll
            for (int pr = 0; pr < 2; pr++) {
                ldsm4(bh[pr], bB + (uint32_t)(pr * 1024));
                ldsm4(bl[pr], bB + OPB + (uint32_t)(pr * 1024));
            }
#pragma unroll
            for (int mt = 0; mt < 4; mt++) {
                uint32_t ah[4], al[4];
                ldsm4(ah, aB + (uint32_t)(mt * 1024));
                ldsm4(al, aB + OPB + (uint32_t)(mt * 1024));
#pragma unroll
                for (int nt = 0; nt < 4; nt++)
                    mma_bf16(acc[mt][nt], ah, &bh[nt >> 1][(nt & 1) * 2]);
#pragma unroll
                for (int nt = 0; nt < 4; nt++)
                    mma_bf16(acc[mt][nt], ah, &bl[nt >> 1][(nt & 1) * 2]);
#pragma unroll
                for (int nt = 0; nt < 4; nt++)
                    mma_bf16(acc[mt][nt], al, &bh[nt >> 1][(nt & 1) * 2]);
            }
        }
        if (++st_idx == NSTG) st_idx = 0;
    }
#undef ISSUE_STAGE

#pragma unroll
    for (int mt = 0; mt < 4; mt++) {
        const int row = m0 + wm * 64 + mt * 16 + g;
#pragma unroll
        for (int nt = 0; nt < 4; nt++) {
            const int col = n0 + wn * 32 + nt * 8 + tig * 2;
            if (Cf) {
                *(float2*)&Cf[(size_t)row * N + col] =
                    make_float2(acc[mt][nt][0], acc[mt][nt][1]);
                *(float2*)&Cf[(size_t)(row + 8) * N + col] =
                    make_float2(acc[mt][nt][2], acc[mt][nt][3]);
            } else {
                uint32_t h0 = packbf(acc[mt][nt][0], acc[mt][nt][1]);
                uint32_t h1 = packbf(acc[mt][nt][2], acc[mt][nt][3]);
                *(uint32_t*)&Chi[(size_t)row * N + col]       = h0;
                *(uint32_t*)&Chi[(size_t)(row + 8) * N + col] = h1;
                *(uint32_t*)&Clo[(size_t)row * N + col] =
                    lopackbf(h0, acc[mt][nt][0], acc[mt][nt][1]);
                *(uint32_t*)&Clo[(size_t)(row + 8) * N + col] =
                    lopackbf(h1, acc[mt][nt][2], acc[mt][nt][3]);
            }
        }
    }
}

// ---------------------------------------------------------------------------
// HMMA flash attention (causal) — byte-identical to round 15 (best)
// ---------------------------------------------------------------------------
#define SKVB   272
#define TILEB  (64 * SKVB)
#define ATTN_SMEM (6 * TILEB)
#define CL2E   (0.08838834764831845f * 1.4426950408889634f)

__global__ __launch_bounds__(128)
void attn_mma(const __nv_bfloat16* __restrict__ qh,
              const __nv_bfloat16* __restrict__ ql,
              __nv_bfloat16* __restrict__ ohi,
              __nv_bfloat16* __restrict__ olo)
{
    extern __shared__ char sma[];
    const uint32_t sb = smem_u32(sma);
    const int qt = (int)gridDim.x - 1 - (int)blockIdx.x;
    const int h = blockIdx.y, b = blockIdx.z;
    const int tid = threadIdx.x, lane = tid & 31, w = tid >> 5;
    const int g = lane >> 2, tig = lane & 3;
    const int lrow = lane & 15, lhalf = lane >> 4;
    const int brow = (lane & 7) | ((lane & 16) >> 1), bhalf = (lane >> 3) & 1;

    const uint32_t sKH = sb,             sKL = sb + TILEB;
    const uint32_t sV0 = sb + 2 * TILEB;

    const size_t qrow0 = (size_t)b * TSEQ + (size_t)qt * 64;

    uint32_t qfh[8][4], qfl[8][4];
    {
        const __nv_bfloat16* qbh = qh + qrow0 * NQKV + h * HD;
        const __nv_bfloat16* qbl = ql + qrow0 * NQKV + h * HD;
#pragma unroll
        for (int it = 0; it < 8; it++) {
            int idx = tid + it * 128;
            int r = idx >> 4, cs = idx & 15;
            uint32_t so = (uint32_t)(r * SKVB + cs * 16);
            size_t go = (size_t)r * NQKV + cs * 8;
            cpa16(sV0 + so, qbh + go);
            cpa16(sV0 + TILEB + so, qbl + go);
        }
        cp_commit();
        cp_wait<0>();
        __syncthreads();
        const uint32_t qAh = sV0 + (uint32_t)((w * 16 + lrow) * SKVB + lhalf * 16);
        const uint32_t qAl = sV0 + TILEB + (uint32_t)((w * 16 + lrow) * SKVB + lhalf * 16);
#pragma unroll
        for (int s = 0; s < 8; s++) {
            ldsm4(qfh[s], qAh + (uint32_t)(s * 32));
            ldsm4(qfl[s], qAl + (uint32_t)(s * 32));
        }
        __syncthreads();
    }

    {
        const size_t kr0 = (size_t)b * TSEQ;
        const __nv_bfloat16* kh = qh + kr0 * NQKV + D_MODEL + h * HD;
        const __nv_bfloat16* kl = ql + kr0 * NQKV + D_MODEL + h * HD;
        const __nv_bfloat16* vh = qh + kr0 * NQKV + 2 * D_MODEL + h * HD;
        const __nv_bfloat16* vl = ql + kr0 * NQKV + 2 * D_MODEL + h * HD;
#pragma unroll
        for (int it = 0; it < 8; it++) {
            int idx = tid + it * 128;
            int r = idx >> 4, cs = idx & 15;
            uint32_t so = (uint32_t)(r * SKVB + cs * 16);
            size_t go = (size_t)r * NQKV + cs * 8;
            cpa16(sKH + so, kh + go);         cpa16(sKL + so, kl + go);
            cpa16(sV0 + so, vh + go);         cpa16(sV0 + TILEB + so, vl + go);
        }
    }
    cp_commit();
    cp_wait<0>();
    __syncthreads();

    float o[16][4];
#pragma unroll
    for (int t = 0; t < 16; t++)
#pragma unroll
        for (int q = 0; q < 4; q++) o[t][q] = 0.0f;
    float mi0 = -1e30f, mi1 = -1e30f, li0 = 0.0f, li1 = 0.0f;

    const uint32_t bH = sKH + (uint32_t)(brow * SKVB + bhalf * 16);
    const uint32_t bL = sKL + (uint32_t)(brow * SKVB + bhalf * 16);
    const uint32_t vOff = (uint32_t)((lane & 15) * SKVB + (lane >> 4) * 16);

    for (int kt = 0; kt <= qt; kt++) {
        float sc[8][4];
#pragma unroll
        for (int nt = 0; nt < 8; nt++)
#pragma unroll
            for (int q = 0; q < 4; q++) sc[nt][q] = 0.0f;

#pragma unroll
        for (int s = 0; s < 8; s++) {
            const uint32_t kb = (uint32_t)(s * 32);
            uint32_t kh4[4][4], kl4[4][4];
#pragma unroll
            for (int p = 0; p < 4; p++) {
                ldsm4(kh4[p], bH + (uint32_t)(p * 16 * SKVB) + kb);
                ldsm4(kl4[p], bL + (uint32_t)(p * 16 * SKVB) + kb);
            }
#pragma unroll
            for (int nt = 0; nt < 8; nt++)
                mma_bf16(sc[nt], qfh[s], &kh4[nt >> 1][(nt & 1) * 2]);
#pragma unroll
            for (int nt = 0; nt < 8; nt++)
                mma_bf16(sc[nt], qfh[s], &kl4[nt >> 1][(nt & 1) * 2]);
#pragma unroll
            for (int nt = 0; nt < 8; nt++)
                mma_bf16(sc[nt], qfl[s], &kh4[nt >> 1][(nt & 1) * 2]);
        }

        if (kt == qt) {
            const int r0 = w * 16 + g, r1 = r0 + 8;
#pragma unroll
            for (int nt = 0; nt < 8; nt++) {
                const int c0 = nt * 8 + 2 * tig;
                if (c0     > r0) sc[nt][0] = -1e30f;
                if (c0 + 1 > r0) sc[nt][1] = -1e30f;
                if (c0     > r1) sc[nt][2] = -1e30f;
                if (c0 + 1 > r1) sc[nt][3] = -1e30f;
            }
        }

        float m0 = -1e30f, m1 = -1e30f;
#pragma unroll
        for (int nt = 0; nt < 8; nt++) {
            m0 = fmaxf(m0, fmaxf(sc[nt][0], sc[nt][1]));
            m1 = fmaxf(m1, fmaxf(sc[nt][2], sc[nt][3]));
        }
        m0 = fmaxf(m0, __shfl_xor_sync(0xffffffffu, m0, 1));
        m0 = fmaxf(m0, __shfl_xor_sync(0xffffffffu, m0, 2));
        m1 = fmaxf(m1, __shfl_xor_sync(0xffffffffu, m1, 1));
        m1 = fmaxf(m1, __shfl_xor_sync(0xffffffffu, m1, 2));
        const float n0 = fmaxf(mi0, m0), n1 = fmaxf(mi1, m1);
        const float c0 = ex2f((mi0 - n0) * CL2E);
        const float c1 = ex2f((mi1 - n1) * CL2E);
        mi0 = n0; mi1 = n1;
        float r0 = 0.0f, r1 = 0.0f;
#pragma unroll
        for (int nt = 0; nt < 8; nt++) {
            sc[nt][0] = ex2f((sc[nt][0] - n0) * CL2E);
            sc[nt][1] = ex2f((sc[nt][1] - n0) * CL2E);
            sc[nt][2] = ex2f((sc[nt][2] - n1) * CL2E);
            sc[nt][3] = ex2f((sc[nt][3] - n1) * CL2E);
            r0 += sc[nt][0] + sc[nt][1];
            r1 += sc[nt][2] + sc[nt][3];
        }
        r0 += __shfl_xor_sync(0xffffffffu, r0, 1);
        r0 += __shfl_xor_sync(0xffffffffu, r0, 2);
        r1 += __shfl_xor_sync(0xffffffffu, r1, 1);
        r1 += __shfl_xor_sync(0xffffffffu, r1, 2);
        li0 = li0 * c0 + r0;
        li1 = li1 * c1 + r1;
#pragma unroll
        for (int t = 0; t < 16; t++) {
            o[t][0] *= c0; o[t][1] *= c0;
            o[t][2] *= c1; o[t][3] *= c1;
        }

        if (kt < qt) {
            __syncthreads();
            const size_t kr0 = (size_t)b * TSEQ + (size_t)(kt + 1) * 64;
            const __nv_bfloat16* kh = qh + kr0 * NQKV + D_MODEL + h * HD;
            const __nv_bfloat16* kl = ql + kr0 * NQKV + D_MODEL + h * HD;
            const __nv_bfloat16* vh = qh + kr0 * NQKV + 2 * D_MODEL + h * HD;
            const __nv_bfloat16* vl = ql + kr0 * NQKV + 2 * D_MODEL + h * HD;
            const uint32_t vDst = sV0 + (uint32_t)(((kt + 1) & 1) * 2) * TILEB;
#pragma unroll
            for (int it = 0; it < 8; it++) {
                int idx = tid + it * 128;
                int r = idx >> 4, cs = idx & 15;
                uint32_t so = (uint32_t)(r * SKVB + cs * 16);
                size_t go = (size_t)r * NQKV + cs * 8;
                cpa16(sKH + so, kh + go);          cpa16(sKL + so, kl + go);
                cpa16(vDst + so, vh + go);         cpa16(vDst + TILEB + so, vl + go);
            }
            cp_commit();
        }

        const uint32_t vCur = sV0 + (uint32_t)((kt & 1) * 2) * TILEB;
        const uint32_t vH = vCur + vOff, vL = vCur + TILEB + vOff;
#pragma unroll
        for (int s = 0; s < 4; s++) {
            uint32_t phi[4], plo[4];
            phi[0] = packbf(sc[2*s][0],   sc[2*s][1]);
            phi[1] = packbf(sc[2*s][2],   sc[2*s][3]);
            phi[2] = packbf(sc[2*s+1][0], sc[2*s+1][1]);
            phi[3] = packbf(sc[2*s+1][2], sc[2*s+1][3]);
            plo[0] = lopackbf(phi[0], sc[2*s][0],   sc[2*s][1]);
            plo[1] = lopackbf(phi[1], sc[2*s][2],   sc[2*s][3]);
            plo[2] = lopackbf(phi[2], sc[2*s+1][0], sc[2*s+1][1]);
            plo[3] = lopackbf(phi[3], sc[2*s+1][2], sc[2*s+1][3]);

            const uint32_t vrow = (uint32_t)(s * 16 * SKVB);
#pragma unroll
            for (int p = 0; p < 8; p++) {
                uint32_t vh4[4], vl4[4];
                ldsm4t(vh4, vH + vrow + (uint32_t)(p * 32));
                ldsm4t(vl4, vL + vrow + (uint32_t)(p * 32));
                mma_bf16(o[2*p],   phi, &vh4[0]);
                mma_bf16(o[2*p+1], phi, &vh4[2]);
                mma_bf16(o[2*p],   plo, &vh4[0]);
                mma_bf16(o[2*p+1], plo, &vh4[2]);
                mma_bf16(o[2*p],   phi, &vl4[0]);
                mma_bf16(o[2*p+1], phi, &vl4[2]);
            }
        }

        if (kt < qt) {
            cp_wait<0>();
            __syncthreads();
        }
    }

    const float inv0 = 1.0f / li0, inv1 = 1.0f / li1;
    const size_t row0 = qrow0 + w * 16 + g, row1 = row0 + 8;
#pragma unroll
    for (int nt = 0; nt < 16; nt++) {
        const int col = h * HD + nt * 8 + 2 * tig;
        float a0 = o[nt][0] * inv0, a1 = o[nt][1] * inv0;
        float a2 = o[nt][2] * inv1, a3 = o[nt][3] * inv1;
        uint32_t h0 = packbf(a0, a1), h1 = packbf(a2, a3);
        *(uint32_t*)&ohi[row0 * D_MODEL + col] = h0;
        *(uint32_t*)&ohi[row1 * D_MODEL + col] = h1;
        *(uint32_t*)&olo[row0 * D_MODEL + col] = lopackbf(h0, a0, a1);
        *(uint32_t*)&olo[row1 * D_MODEL + col] = lopackbf(h1, a2, a3);
    }
}

// ---------------------------------------------------------------------------
extern "C" void kernel_launch(void* const* d_in, const int* in_sizes, int n_in,
                              void* d_out, int out_size)
{
    (void)in_sizes; (void)n_in; (void)out_size;
    const float* x      = (const float*)d_in[0];
    const float* w_qkv  = (const float*)d_in[1];
    const float* w_proj = (const float*)d_in[2];
    float* out = (float*)d_out;

    __nv_bfloat16 *qhi, *qlo, *xhi, *xlo, *ahi, *alo, *wqhi, *wqlo, *wphi, *wplo;
    cudaGetSymbolAddress((void**)&qhi,  g_qkvhi);
    cudaGetSymbolAddress((void**)&qlo,  g_qkvlo);
    cudaGetSymbolAddress((void**)&xhi,  g_xhi);
    cudaGetSymbolAddress((void**)&xlo,  g_xlo);
    cudaGetSymbolAddress((void**)&ahi,  g_ahi);
    cudaGetSymbolAddress((void**)&alo,  g_alo);
    cudaGetSymbolAddress((void**)&wqhi, g_wqhi);
    cudaGetSymbolAddress((void**)&wqlo, g_wqlo);
    cudaGetSymbolAddress((void**)&wphi, g_wphi);
    cudaGetSymbolAddress((void**)&wplo, g_wplo);

    cudaFuncSetAttribute(gemm_hmma,
                         cudaFuncAttributeMaxDynamicSharedMemorySize, GEMM_SMEM);
    cudaFuncSetAttribute(attn_mma,
                         cudaFuncAttributeMaxDynamicSharedMemorySize, ATTN_SMEM);

    const int nx = MTOT * D_MODEL;

    split_kernel<<<nx / 4 / 256, 256>>>(x, xhi, xlo, nx);
    tsplit_kernel<<<dim3(NQKV / 32, D_MODEL / 32), 256>>>(w_qkv, wqhi, wqlo,
                                                          D_MODEL, NQKV);
    tsplit_kernel<<<dim3(D_MODEL / 32, D_MODEL / 32), 256>>>(w_proj, wphi, wplo,
                                                             D_MODEL, D_MODEL);
    gemm_hmma<<<dim3(NQKV / 128, MTOT / 128), 256, GEMM_SMEM>>>(
        xhi, xlo, wqhi, wqlo, nullptr, qhi, qlo, MTOT, NQKV, D_MODEL);
    attn_mma<<<dim3(TSEQ / 64, NHEAD, BATCH), 128, ATTN_SMEM>>>(
        qhi, qlo, ahi, alo);
    gemm_hmma<<<dim3(D_MODEL / 128, MTOT / 128), 256, GEMM_SMEM>>>(
        ahi, alo, wphi, wplo, out, nullptr, nullptr, MTOT, D_MODEL, D_MODEL);
}

// round 17
// speedup vs baseline: 1.0678x; 1.0678x over previous
#include <cuda_runtime.h>
#include <cuda_bf16.h>
#include <cstdint>

#define D_MODEL 2048
#define NHEAD   16
#define HD      128
#define TSEQ    1024
#define BATCH   4
#define MTOT    (BATCH * TSEQ)     // 4096
#define NQKV    (3 * D_MODEL)      // 6144

// QKV tiling: 48 x 32 = 1536 tiles of 128x128; last 56 are K-split 4-way
#define QKV_NTX     48
#define QKV_TILES   1536
#define QKV_FULL    1480
#define QKV_SPLIT   (QKV_TILES - QKV_FULL)       // 56
#define QKV_GRID    (QKV_FULL + 4 * QKV_SPLIT)   // 1704

// ---------------------------------------------------------------------------
// Scratch (__device__ globals — allocation-guard safe), 16B-aligned
// ---------------------------------------------------------------------------
__device__ __align__(16) __nv_bfloat16 g_qkvhi[MTOT * NQKV];
__device__ __align__(16) __nv_bfloat16 g_qkvlo[MTOT * NQKV];
__device__ __align__(16) __nv_bfloat16 g_xhi[MTOT * D_MODEL];
__device__ __align__(16) __nv_bfloat16 g_xlo[MTOT * D_MODEL];
__device__ __align__(16) __nv_bfloat16 g_ahi[MTOT * D_MODEL];
__device__ __align__(16) __nv_bfloat16 g_alo[MTOT * D_MODEL];
__device__ __align__(16) __nv_bfloat16 g_wqhi[NQKV * D_MODEL];
__device__ __align__(16) __nv_bfloat16 g_wqlo[NQKV * D_MODEL];
__device__ __align__(16) __nv_bfloat16 g_wphi[D_MODEL * D_MODEL];
__device__ __align__(16) __nv_bfloat16 g_wplo[D_MODEL * D_MODEL];
__device__ __align__(16) float g_part[4 * QKV_SPLIT * 128 * 128];   // 14.7 MB

// ---------------------------------------------------------------------------
// helpers
// ---------------------------------------------------------------------------
__device__ __forceinline__ uint32_t smem_u32(const void* p) {
    uint32_t a;
    asm("{ .reg .u64 t; cvta.to.shared.u64 t, %1; cvt.u32.u64 %0, t; }"
        : "=r"(a) : "l"(p));
    return a;
}
__device__ __forceinline__ void cpa16(uint32_t dst, const void* src) {
    asm volatile("cp.async.cg.shared.global [%0], [%1], 16;" :: "r"(dst), "l"(src));
}
__device__ __forceinline__ void cp_commit() { asm volatile("cp.async.commit_group;"); }
template <int N> __device__ __forceinline__ void cp_wait() {
    asm volatile("cp.async.wait_group %0;" :: "n"(N));
}
__device__ __forceinline__ void ldsm4(uint32_t* r, uint32_t a) {
    asm volatile("ldmatrix.sync.aligned.m8n8.x4.shared.b16 {%0,%1,%2,%3}, [%4];"
        : "=r"(r[0]), "=r"(r[1]), "=r"(r[2]), "=r"(r[3]) : "r"(a));
}
__device__ __forceinline__ void ldsm4t(uint32_t* r, uint32_t a) {
    asm volatile("ldmatrix.sync.aligned.m8n8.x4.trans.shared.b16 {%0,%1,%2,%3}, [%4];"
        : "=r"(r[0]), "=r"(r[1]), "=r"(r[2]), "=r"(r[3]) : "r"(a));
}
__device__ __forceinline__ void mma_bf16(float* c, const uint32_t* a,
                                         const uint32_t* b) {
    asm volatile(
        "mma.sync.aligned.m16n8k16.row.col.f32.bf16.bf16.f32 "
        "{%0,%1,%2,%3}, {%4,%5,%6,%7}, {%8,%9}, {%0,%1,%2,%3};"
        : "+f"(c[0]), "+f"(c[1]), "+f"(c[2]), "+f"(c[3])
        : "r"(a[0]), "r"(a[1]), "r"(a[2]), "r"(a[3]), "r"(b[0]), "r"(b[1]));
}
__device__ __forceinline__ uint32_t packbf(float e0, float e1) {
    uint32_t r;
    asm("cvt.rn.bf16x2.f32 %0, %1, %2;" : "=r"(r) : "f"(e1), "f"(e0));
    return r;
}
__device__ __forceinline__ uint32_t lopackbf(uint32_t hipack, float e0, float e1) {
    float h0 = __uint_as_float(hipack << 16);
    float h1 = __uint_as_float(hipack & 0xffff0000u);
    return packbf(e0 - h0, e1 - h1);
}
__device__ __forceinline__ float ex2f(float x) {
    float y;
    asm("ex2.approx.ftz.f32 %0, %1;" : "=f"(y) : "f"(x));
    return y;
}
// 64B-row swizzle: bits [4:5] ^= bits [7:8]; apply to full sub-bit-10 offset.
__device__ __forceinline__ uint32_t swz(uint32_t off) {
    return off ^ (((off >> 7) & 3u) << 4);
}

// ---------------------------------------------------------------------------
// Split fp32 -> (hi, lo) bf16 (elementwise)
// ---------------------------------------------------------------------------
__global__ __launch_bounds__(256)
void split_kernel(const float* __restrict__ in, __nv_bfloat16* __restrict__ hi,
                  __nv_bfloat16* __restrict__ lo, int n)
{
    int i = (blockIdx.x * 256 + threadIdx.x) * 4;
    if (i >= n) return;
    float4 v = *(const float4*)(in + i);
    uint32_t h0 = packbf(v.x, v.y);
    uint32_t h1 = packbf(v.z, v.w);
    *(uint32_t*)(hi + i)     = h0;
    *(uint32_t*)(hi + i + 2) = h1;
    *(uint32_t*)(lo + i)     = lopackbf(h0, v.x, v.y);
    *(uint32_t*)(lo + i + 2) = lopackbf(h1, v.z, v.w);
}

// ---------------------------------------------------------------------------
// Transpose + split: W fp32 [K][N] -> Whi/Wlo bf16 [N][K]
// ---------------------------------------------------------------------------
__global__ __launch_bounds__(256)
void tsplit_kernel(const float* __restrict__ W, __nv_bfloat16* __restrict__ hi,
                   __nv_bfloat16* __restrict__ lo, int K, int N)
{
    __shared__ float t[32][33];
    const int n0 = blockIdx.x * 32, k0 = blockIdx.y * 32;
    const int x = threadIdx.x & 31, y = threadIdx.x >> 5;
#pragma unroll
    for (int i = 0; i < 4; i++)
        t[y + 8 * i][x] = W[(size_t)(k0 + y + 8 * i) * N + n0 + x];
    __syncthreads();
#pragma unroll
    for (int i = 0; i < 4; i++) {
        float v = t[x][y + 8 * i];
        __nv_bfloat16 h = __float2bfloat16(v);
        size_t o = (size_t)(n0 + y + 8 * i) * K + k0 + x;
        hi[o] = h;
        lo[o] = __float2bfloat16(v - __bfloat162float(h));
    }
}

// ---------------------------------------------------------------------------
// HMMA bf16x3 GEMM — R15 pipeline, 1-D grid. CTAs with bid >= fullTiles are
// quarter-K split CTAs for the tail tiles: they compute K/4 and write fp32
// partials (wave-quantization fix: the tail wave runs at 1/4 duration).
// ---------------------------------------------------------------------------
#define BKC        32
#define OPB        (128 * 64)
#define STGB       (4 * OPB)
#define NSTG       3
#define GEMM_SMEM  (NSTG * STGB)

__device__ __forceinline__ void load_op(uint32_t dstb,
                                        const __nv_bfloat16* __restrict__ src,
                                        int r0, int k0, int K, int tid)
{
#pragma unroll
    for (int t = 0; t < 2; t++) {
        const int i = tid + t * 256;
        const int row = i >> 2, seg = i & 3;
        cpa16(dstb + swz((uint32_t)(row * 64 + seg * 16)),
              src + (size_t)(r0 + row) * K + k0 + seg * 8);
    }
}

__device__ __forceinline__ void load_stage(
    uint32_t sbase,
    const __nv_bfloat16* __restrict__ Ahi, const __nv_bfloat16* __restrict__ Alo,
    const __nv_bfloat16* __restrict__ Bhi, const __nv_bfloat16* __restrict__ Blo,
    int m0, int n0, int k0, int K, int tid)
{
    load_op(sbase + 0 * OPB, Ahi, m0, k0, K, tid);
    load_op(sbase + 1 * OPB, Alo, m0, k0, K, tid);
    load_op(sbase + 2 * OPB, Bhi, n0, k0, K, tid);
    load_op(sbase + 3 * OPB, Blo, n0, k0, K, tid);
}

__global__ __launch_bounds__(256, 2)
void gemm_hmma(const __nv_bfloat16* __restrict__ Ahi,
               const __nv_bfloat16* __restrict__ Alo,
               const __nv_bfloat16* __restrict__ Bhi,
               const __nv_bfloat16* __restrict__ Blo,
               float* __restrict__ Cf,
               __nv_bfloat16* __restrict__ Chi,
               __nv_bfloat16* __restrict__ Clo,
               float* __restrict__ Part,
               int M, int N, int K, int fullTiles, int ntx)
{
    extern __shared__ char smc[];
    const uint32_t sb = smem_u32(smc);
    const int tid  = threadIdx.x;
    const int wid  = tid >> 5, lane = tid & 31;
    const int wm   = wid >> 2;
    const int wn   = wid & 3;
    const int g    = lane >> 2;
    const int tig  = lane & 3;

    const int bid = blockIdx.x;
    const bool isPart = (bid >= fullTiles);
    int tile, k0, NCl;
    if (isPart) {
        const int s = bid - fullTiles;
        tile = fullTiles + (s >> 2);
        k0   = (s & 3) * (K >> 2);
        NCl  = (K >> 2) / BKC;
    } else {
        tile = bid; k0 = 0; NCl = K / BKC;
    }
    const int m0 = (tile / ntx) * 128, n0 = (tile % ntx) * 128;

    const int lrow  = lane & 15;
    const int lhalf = lane >> 4;
    const int brow  = (lane & 7) | ((lane & 16) >> 1);
    const int bhalf = (lane >> 3) & 1;

    uint32_t aoff[2], boff[2];
#pragma unroll
    for (int ks = 0; ks < 2; ks++) {
        aoff[ks] = swz((uint32_t)((wm * 64 + lrow) * 64 + lhalf * 16 + ks * 32));
        boff[ks] = swz((uint32_t)((wn * 32 + brow) * 64 + bhalf * 16 + ks * 32));
    }

    float acc[4][4][4];
#pragma unroll
    for (int mt = 0; mt < 4; mt++)
#pragma unroll
        for (int nt = 0; nt < 4; nt++)
#pragma unroll
            for (int q = 0; q < 4; q++) acc[mt][nt][q] = 0.0f;

    load_stage(sb, Ahi, Alo, Bhi, Blo, m0, n0, k0, K, tid);
    cp_commit();
    load_stage(sb + STGB, Ahi, Alo, Bhi, Blo, m0, n0, k0 + BKC, K, tid);
    cp_commit();

    int st_idx = 0;
    for (int kc = 0; kc < NCl; kc++) {
        if (kc + 1 < NCl) cp_wait<1>(); else cp_wait<0>();
        __syncthreads();

        if (kc + 2 < NCl) {
            int nst = st_idx + 2; if (nst >= NSTG) nst -= NSTG;
            load_stage(sb + (uint32_t)nst * STGB,
                       Ahi, Alo, Bhi, Blo, m0, n0, k0 + (kc + 2) * BKC, K, tid);
            cp_commit();
        }

        const uint32_t st = sb + (uint32_t)st_idx * STGB;
#pragma unroll
        for (int ks = 0; ks < 2; ks++) {
            const uint32_t aB = st + aoff[ks];
            const uint32_t bB = st + 2u * OPB + boff[ks];

            uint32_t bh[2][4], bl[2][4];
#pragma unroll
            for (int pr = 0; pr < 2; pr++) {
                ldsm4(bh[pr], bB + (uint32_t)(pr * 1024));
                ldsm4(bl[pr], bB + OPB + (uint32_t)(pr * 1024));
            }
#pragma unroll
            for (int mt = 0; mt < 4; mt++) {
                uint32_t ah[4], al[4];
                ldsm4(ah, aB + (uint32_t)(mt * 1024));
                ldsm4(al, aB + OPB + (uint32_t)(mt * 1024));
#pragma unroll
                for (int nt = 0; nt < 4; nt++)
                    mma_bf16(acc[mt][nt], ah, &bh[nt >> 1][(nt & 1) * 2]);
#pragma unroll
                for (int nt = 0; nt < 4; nt++)
                    mma_bf16(acc[mt][nt], ah, &bl[nt >> 1][(nt & 1) * 2]);
#pragma unroll
                for (int nt = 0; nt < 4; nt++)
                    mma_bf16(acc[mt][nt], al, &bh[nt >> 1][(nt & 1) * 2]);
            }
        }
        if (++st_idx == NSTG) st_idx = 0;
    }

    if (isPart) {
        // write fp32 partial tile (local 128x128 layout)
        float* pp = Part + (size_t)(bid - fullTiles) * 16384;
#pragma unroll
        for (int mt = 0; mt < 4; mt++) {
            const int row = wm * 64 + mt * 16 + g;
#pragma unroll
            for (int nt = 0; nt < 4; nt++) {
                const int col = wn * 32 + nt * 8 + tig * 2;
                *(float2*)&pp[(row)     * 128 + col] =
                    make_float2(acc[mt][nt][0], acc[mt][nt][1]);
                *(float2*)&pp[(row + 8) * 128 + col] =
                    make_float2(acc[mt][nt][2], acc[mt][nt][3]);
            }
        }
        return;
    }

#pragma unroll
    for (int mt = 0; mt < 4; mt++) {
        const int row = m0 + wm * 64 + mt * 16 + g;
#pragma unroll
        for (int nt = 0; nt < 4; nt++) {
            const int col = n0 + wn * 32 + nt * 8 + tig * 2;
            if (Cf) {
                *(float2*)&Cf[(size_t)row * N + col] =
                    make_float2(acc[mt][nt][0], acc[mt][nt][1]);
                *(float2*)&Cf[(size_t)(row + 8) * N + col] =
                    make_float2(acc[mt][nt][2], acc[mt][nt][3]);
            } else {
                uint32_t h0 = packbf(acc[mt][nt][0], acc[mt][nt][1]);
                uint32_t h1 = packbf(acc[mt][nt][2], acc[mt][nt][3]);
                *(uint32_t*)&Chi[(size_t)row * N + col]       = h0;
                *(uint32_t*)&Chi[(size_t)(row + 8) * N + col] = h1;
                *(uint32_t*)&Clo[(size_t)row * N + col] =
                    lopackbf(h0, acc[mt][nt][0], acc[mt][nt][1]);
                *(uint32_t*)&Clo[(size_t)(row + 8) * N + col] =
                    lopackbf(h1, acc[mt][nt][2], acc[mt][nt][3]);
            }
        }
    }
}

// ---------------------------------------------------------------------------
// Reduce the 4 K-partials of each tail tile (deterministic fixed order) and
// emit split bf16. grid = (16, QKV_SPLIT), 256 threads, 4 floats/thread.
// ---------------------------------------------------------------------------
__global__ __launch_bounds__(256)
void ksum_kernel(const float* __restrict__ Part,
                 __nv_bfloat16* __restrict__ Chi, __nv_bfloat16* __restrict__ Clo,
                 int fullTiles, int ntx, int N)
{
    const int st = blockIdx.y;
    const int tile = fullTiles + st;
    const int e = (blockIdx.x * 256 + threadIdx.x) * 4;   // 0..16380
    const float* p = Part + (size_t)st * 4 * 16384 + e;
    float4 a = *(const float4*)p;
    float4 b = *(const float4*)(p + 16384);
    float4 c = *(const float4*)(p + 2 * 16384);
    float4 d = *(const float4*)(p + 3 * 16384);
    float s0 = ((a.x + b.x) + c.x) + d.x;
    float s1 = ((a.y + b.y) + c.y) + d.y;
    float s2 = ((a.z + b.z) + c.z) + d.z;
    float s3 = ((a.w + b.w) + c.w) + d.w;
    const int row = e >> 7, col = e & 127;
    const size_t grow = (size_t)(tile / ntx) * 128 + row;
    const size_t gcol = (size_t)(tile % ntx) * 128 + col;
    uint32_t h0 = packbf(s0, s1), h1 = packbf(s2, s3);
    *(uint32_t*)&Chi[grow * N + gcol]     = h0;
    *(uint32_t*)&Chi[grow * N + gcol + 2] = h1;
    *(uint32_t*)&Clo[grow * N + gcol]     = lopackbf(h0, s0, s1);
    *(uint32_t*)&Clo[grow * N + gcol + 2] = lopackbf(h1, s2, s3);
}

// ---------------------------------------------------------------------------
// HMMA flash attention (causal) — byte-identical to round 15 (best)
// ---------------------------------------------------------------------------
#define SKVB   272
#define TILEB  (64 * SKVB)
#define ATTN_SMEM (6 * TILEB)
#define CL2E   (0.08838834764831845f * 1.4426950408889634f)

__global__ __launch_bounds__(128)
void attn_mma(const __nv_bfloat16* __restrict__ qh,
              const __nv_bfloat16* __restrict__ ql,
              __nv_bfloat16* __restrict__ ohi,
              __nv_bfloat16* __restrict__ olo)
{
    extern __shared__ char sma[];
    const uint32_t sb = smem_u32(sma);
    const int qt = (int)gridDim.x - 1 - (int)blockIdx.x;
    const int h = blockIdx.y, b = blockIdx.z;
    const int tid = threadIdx.x, lane = tid & 31, w = tid >> 5;
    const int g = lane >> 2, tig = lane & 3;
    const int lrow = lane & 15, lhalf = lane >> 4;
    const int brow = (lane & 7) | ((lane & 16) >> 1), bhalf = (lane >> 3) & 1;

    const uint32_t sKH = sb,             sKL = sb + TILEB;
    const uint32_t sV0 = sb + 2 * TILEB;

    const size_t qrow0 = (size_t)b * TSEQ + (size_t)qt * 64;

    uint32_t qfh[8][4], qfl[8][4];
    {
        const __nv_bfloat16* qbh = qh + qrow0 * NQKV + h * HD;
        const __nv_bfloat16* qbl = ql + qrow0 * NQKV + h * HD;
#pragma unroll
        for (int it = 0; it < 8; it++) {
            int idx = tid + it * 128;
            int r = idx >> 4, cs = idx & 15;
            uint32_t so = (uint32_t)(r * SKVB + cs * 16);
            size_t go = (size_t)r * NQKV + cs * 8;
            cpa16(sV0 + so, qbh + go);
            cpa16(sV0 + TILEB + so, qbl + go);
        }
        cp_commit();
        cp_wait<0>();
        __syncthreads();
        const uint32_t qAh = sV0 + (uint32_t)((w * 16 + lrow) * SKVB + lhalf * 16);
        const uint32_t qAl = sV0 + TILEB + (uint32_t)((w * 16 + lrow) * SKVB + lhalf * 16);
#pragma unroll
        for (int s = 0; s < 8; s++) {
            ldsm4(qfh[s], qAh + (uint32_t)(s * 32));
            ldsm4(qfl[s], qAl + (uint32_t)(s * 32));
        }
        __syncthreads();
    }

    {
        const size_t kr0 = (size_t)b * TSEQ;
        const __nv_bfloat16* kh = qh + kr0 * NQKV + D_MODEL + h * HD;
        const __nv_bfloat16* kl = ql + kr0 * NQKV + D_MODEL + h * HD;
        const __nv_bfloat16* vh = qh + kr0 * NQKV + 2 * D_MODEL + h * HD;
        const __nv_bfloat16* vl = ql + kr0 * NQKV + 2 * D_MODEL + h * HD;
#pragma unroll
        for (int it = 0; it < 8; it++) {
            int idx = tid + it * 128;
            int r = idx >> 4, cs = idx & 15;
            uint32_t so = (uint32_t)(r * SKVB + cs * 16);
            size_t go = (size_t)r * NQKV + cs * 8;
            cpa16(sKH + so, kh + go);         cpa16(sKL + so, kl + go);
            cpa16(sV0 + so, vh + go);         cpa16(sV0 + TILEB + so, vl + go);
        }
    }
    cp_commit();
    cp_wait<0>();
    __syncthreads();

    float o[16][4];
#pragma unroll
    for (int t = 0; t < 16; t++)
#pragma unroll
        for (int q = 0; q < 4; q++) o[t][q] = 0.0f;
    float mi0 = -1e30f, mi1 = -1e30f, li0 = 0.0f, li1 = 0.0f;

    const uint32_t bH = sKH + (uint32_t)(brow * SKVB + bhalf * 16);
    const uint32_t bL = sKL + (uint32_t)(brow * SKVB + bhalf * 16);
    const uint32_t vOff = (uint32_t)((lane & 15) * SKVB + (lane >> 4) * 16);

    for (int kt = 0; kt <= qt; kt++) {
        float sc[8][4];
#pragma unroll
        for (int nt = 0; nt < 8; nt++)
#pragma unroll
            for (int q = 0; q < 4; q++) sc[nt][q] = 0.0f;

#pragma unroll
        for (int s = 0; s < 8; s++) {
            const uint32_t kb = (uint32_t)(s * 32);
            uint32_t kh4[4][4], kl4[4][4];
#pragma unroll
            for (int p = 0; p < 4; p++) {
                ldsm4(kh4[p], bH + (uint32_t)(p * 16 * SKVB) + kb);
                ldsm4(kl4[p], bL + (uint32_t)(p * 16 * SKVB) + kb);
            }
#pragma unroll
            for (int nt = 0; nt < 8; nt++)
                mma_bf16(sc[nt], qfh[s], &kh4[nt >> 1][(nt & 1) * 2]);
#pragma unroll
            for (int nt = 0; nt < 8; nt++)
                mma_bf16(sc[nt], qfh[s], &kl4[nt >> 1][(nt & 1) * 2]);
#pragma unroll
            for (int nt = 0; nt < 8; nt++)
                mma_bf16(sc[nt], qfl[s], &kh4[nt >> 1][(nt & 1) * 2]);
        }

        if (kt == qt) {
            const int r0 = w * 16 + g, r1 = r0 + 8;
#pragma unroll
            for (int nt = 0; nt < 8; nt++) {
                const int c0 = nt * 8 + 2 * tig;
                if (c0     > r0) sc[nt][0] = -1e30f;
                if (c0 + 1 > r0) sc[nt][1] = -1e30f;
                if (c0     > r1) sc[nt][2] = -1e30f;
                if (c0 + 1 > r1) sc[nt][3] = -1e30f;
            }
        }

        float m0 = -1e30f, m1 = -1e30f;
#pragma unroll
        for (int nt = 0; nt < 8; nt++) {
            m0 = fmaxf(m0, fmaxf(sc[nt][0], sc[nt][1]));
            m1 = fmaxf(m1, fmaxf(sc[nt][2], sc[nt][3]));
        }
        m0 = fmaxf(m0, __shfl_xor_sync(0xffffffffu, m0, 1));
        m0 = fmaxf(m0, __shfl_xor_sync(0xffffffffu, m0, 2));
        m1 = fmaxf(m1, __shfl_xor_sync(0xffffffffu, m1, 1));
        m1 = fmaxf(m1, __shfl_xor_sync(0xffffffffu, m1, 2));
        const float n0 = fmaxf(mi0, m0), n1 = fmaxf(mi1, m1);
        const float c0 = ex2f((mi0 - n0) * CL2E);
        const float c1 = ex2f((mi1 - n1) * CL2E);
        mi0 = n0; mi1 = n1;
        float r0 = 0.0f, r1 = 0.0f;
#pragma unroll
        for (int nt = 0; nt < 8; nt++) {
            sc[nt][0] = ex2f((sc[nt][0] - n0) * CL2E);
            sc[nt][1] = ex2f((sc[nt][1] - n0) * CL2E);
            sc[nt][2] = ex2f((sc[nt][2] - n1) * CL2E);
            sc[nt][3] = ex2f((sc[nt][3] - n1) * CL2E);
            r0 += sc[nt][0] + sc[nt][1];
            r1 += sc[nt][2] + sc[nt][3];
        }
        r0 += __shfl_xor_sync(0xffffffffu, r0, 1);
        r0 += __shfl_xor_sync(0xffffffffu, r0, 2);
        r1 += __shfl_xor_sync(0xffffffffu, r1, 1);
        r1 += __shfl_xor_sync(0xffffffffu, r1, 2);
        li0 = li0 * c0 + r0;
        li1 = li1 * c1 + r1;
#pragma unroll
        for (int t = 0; t < 16; t++) {
            o[t][0] *= c0; o[t][1] *= c0;
            o[t][2] *= c1; o[t][3] *= c1;
        }

        if (kt < qt) {
            __syncthreads();
            const size_t kr0 = (size_t)b * TSEQ + (size_t)(kt + 1) * 64;
            const __nv_bfloat16* kh = qh + kr0 * NQKV + D_MODEL + h * HD;
            const __nv_bfloat16* kl = ql + kr0 * NQKV + D_MODEL + h * HD;
            const __nv_bfloat16* vh = qh + kr0 * NQKV + 2 * D_MODEL + h * HD;
            const __nv_bfloat16* vl = ql + kr0 * NQKV + 2 * D_MODEL + h * HD;
            const uint32_t vDst = sV0 + (uint32_t)(((kt + 1) & 1) * 2) * TILEB;
#pragma unroll
            for (int it = 0; it < 8; it++) {
                int idx = tid + it * 128;
                int r = idx >> 4, cs = idx & 15;
                uint32_t so = (uint32_t)(r * SKVB + cs * 16);
                size_t go = (size_t)r * NQKV + cs * 8;
                cpa16(sKH + so, kh + go);          cpa16(sKL + so, kl + go);
                cpa16(vDst + so, vh + go);         cpa16(vDst + TILEB + so, vl + go);
            }
            cp_commit();
        }

        const uint32_t vCur = sV0 + (uint32_t)((kt & 1) * 2) * TILEB;
        const uint32_t vH = vCur + vOff, vL = vCur + TILEB + vOff;
#pragma unroll
        for (int s = 0; s < 4; s++) {
            uint32_t phi[4], plo[4];
            phi[0] = packbf(sc[2*s][0],   sc[2*s][1]);
            phi[1] = packbf(sc[2*s][2],   sc[2*s][3]);
            phi[2] = packbf(sc[2*s+1][0], sc[2*s+1][1]);
            phi[3] = packbf(sc[2*s+1][2], sc[2*s+1][3]);
            plo[0] = lopackbf(phi[0], sc[2*s][0],   sc[2*s][1]);
            plo[1] = lopackbf(phi[1], sc[2*s][2],   sc[2*s][3]);
            plo[2] = lopackbf(phi[2], sc[2*s+1][0], sc[2*s+1][1]);
            plo[3] = lopackbf(phi[3], sc[2*s+1][2], sc[2*s+1][3]);

            const uint32_t vrow = (uint32_t)(s * 16 * SKVB);
#pragma unroll
            for (int p = 0; p < 8; p++) {
                uint32_t vh4[4], vl4[4];
                ldsm4t(vh4, vH + vrow + (uint32_t)(p * 32));
                ldsm4t(vl4, vL + vrow + (uint32_t)(p * 32));
                mma_bf16(o[2*p],   phi, &vh4[0]);
                mma_bf16(o[2*p+1], phi, &vh4[2]);
                mma_bf16(o[2*p],   plo, &vh4[0]);
                mma_bf16(o[2*p+1], plo, &vh4[2]);
                mma_bf16(o[2*p],   phi, &vl4[0]);
                mma_bf16(o[2*p+1], phi, &vl4[2]);
            }
        }

        if (kt < qt) {
            cp_wait<0>();
            __syncthreads();
        }
    }

    const float inv0 = 1.0f / li0, inv1 = 1.0f / li1;
    const size_t row0 = qrow0 + w * 16 + g, row1 = row0 + 8;
#pragma unroll
    for (int nt = 0; nt < 16; nt++) {
        const int col = h * HD + nt * 8 + 2 * tig;
        float a0 = o[nt][0] * inv0, a1 = o[nt][1] * inv0;
        float a2 = o[nt][2] * inv1, a3 = o[nt][3] * inv1;
        uint32_t h0 = packbf(a0, a1), h1 = packbf(a2, a3);
        *(uint32_t*)&ohi[row0 * D_MODEL + col] = h0;
        *(uint32_t*)&ohi[row1 * D_MODEL + col] = h1;
        *(uint32_t*)&olo[row0 * D_MODEL + col] = lopackbf(h0, a0, a1);
        *(uint32_t*)&olo[row1 * D_MODEL + col] = lopackbf(h1, a2, a3);
    }
}

// ---------------------------------------------------------------------------
extern "C" void kernel_launch(void* const* d_in, const int* in_sizes, int n_in,
                              void* d_out, int out_size)
{
    (void)in_sizes; (void)n_in; (void)out_size;
    const float* x      = (const float*)d_in[0];
    const float* w_qkv  = (const float*)d_in[1];
    const float* w_proj = (const float*)d_in[2];
    float* out = (float*)d_out;

    __nv_bfloat16 *qhi, *qlo, *xhi, *xlo, *ahi, *alo, *wqhi, *wqlo, *wphi, *wplo;
    float* part;
    cudaGetSymbolAddress((void**)&qhi,  g_qkvhi);
    cudaGetSymbolAddress((void**)&qlo,  g_qkvlo);
    cudaGetSymbolAddress((void**)&xhi,  g_xhi);
    cudaGetSymbolAddress((void**)&xlo,  g_xlo);
    cudaGetSymbolAddress((void**)&ahi,  g_ahi);
    cudaGetSymbolAddress((void**)&alo,  g_alo);
    cudaGetSymbolAddress((void**)&wqhi, g_wqhi);
    cudaGetSymbolAddress((void**)&wqlo, g_wqlo);
    cudaGetSymbolAddress((void**)&wphi, g_wphi);
    cudaGetSymbolAddress((void**)&wplo, g_wplo);
    cudaGetSymbolAddress((void**)&part, g_part);

    cudaFuncSetAttribute(gemm_hmma,
                         cudaFuncAttributeMaxDynamicSharedMemorySize, GEMM_SMEM);
    cudaFuncSetAttribute(attn_mma,
                         cudaFuncAttributeMaxDynamicSharedMemorySize, ATTN_SMEM);

    const int nx = MTOT * D_MODEL;

    split_kernel<<<nx / 4 / 256, 256>>>(x, xhi, xlo, nx);
    tsplit_kernel<<<dim3(NQKV / 32, D_MODEL / 32), 256>>>(w_qkv, wqhi, wqlo,
                                                          D_MODEL, NQKV);
    tsplit_kernel<<<dim3(D_MODEL / 32, D_MODEL / 32), 256>>>(w_proj, wphi, wplo,
                                                             D_MODEL, D_MODEL);
    // qkv = x @ w_qkv : 1480 full tiles + 56 tail tiles K-split 4-way
    gemm_hmma<<<QKV_GRID, 256, GEMM_SMEM>>>(
        xhi, xlo, wqhi, wqlo, nullptr, qhi, qlo, part,
        MTOT, NQKV, D_MODEL, QKV_FULL, QKV_NTX);
    ksum_kernel<<<dim3(16, QKV_SPLIT), 256>>>(part, qhi, qlo,
                                              QKV_FULL, QKV_NTX, NQKV);
    // attention
    attn_mma<<<dim3(TSEQ / 64, NHEAD, BATCH), 128, ATTN_SMEM>>>(
        qhi, qlo, ahi, alo);
    // out = att @ w_proj : 512 tiles, no split
    gemm_hmma<<<D_MODEL / 128 * (MTOT / 128), 256, GEMM_SMEM>>>(
        ahi, alo, wphi, wplo, out, nullptr, nullptr, nullptr,
        MTOT, D_MODEL, D_MODEL, 1 << 30, D_MODEL / 128);
}